// round 16
// baseline (speedup 1.0000x reference)
#include <cuda_runtime.h>

#define BN   16
#define CN   80
#define HN   128
#define WN   128
#define HWN  (HN*WN)
#define NPLANES (BN*CN)
#define TOPK 100
#define NB1  2048
#define SBUF 2560                   // shared candidate cap per plane (expected ~1820)
#define SCMP 1024                   // staging cap for plane survivors (expected ~130)
#define BCAP2 16384                 // per-batch contiguous candidate cap (expected ~10.4k)
#define SCAP 2048                   // per-batch survivor cap (expected ~700)
#define RCAP 1024                   // refined cap (expected ~101)
#define LCAP 32                     // per-thread keep cap (strict bound for tie-free data)
#define FULLM 0xffffffffu
#define NEG_INF __int_as_float(0xff800000)

// ---- scratch (device globals; allocation-free contract) ----
__device__ unsigned long long g_bcand[BN][BCAP2]; // contiguous per-batch candidates
__device__ int g_bcnt[BN];                        // zero at load; consumer-reset by K2
__device__ int g_hist[BN][NB1];                   // zero at load; consumer-reset by K2

__device__ __forceinline__ int bin1f(float v){
    int b = (int)(v * 2048.0f);
    return b < 0 ? 0 : (b > NB1-1 ? NB1-1 : b);
}
__device__ __forceinline__ int bin2f(float v, int b1){
    float f = v * 2048.0f - (float)b1;
    int b = (int)(f * 2048.0f);
    return b < 0 ? 0 : (b > NB1-1 ? NB1-1 : b);
}

// Warp-serial suffix cut scan: largest bin with initAcc+suffix >= TOPK,
// also returning the count at/above that bin. Call from one full warp.
__device__ __forceinline__ void cut_scan2(const int* h, int initAcc, int lane,
                                          int* cutO, int* cntO){
    int acc = initAcc, cut = 0, cnt = -1;
    for (int bb = NB1 - 32; bb >= 0; bb -= 32){
        int suf = h[bb + lane];
        #pragma unroll
        for (int off = 1; off < 32; off <<= 1){
            int t = __shfl_down_sync(FULLM, suf, off);
            if (lane + off < 32) suf += t;
        }
        unsigned bal = __ballot_sync(FULLM, acc + suf >= TOPK);
        if (bal){
            int L = 31 - __clz(bal);
            cut = bb + L;
            cnt = acc + __shfl_sync(FULLM, suf, L);
            break;
        }
        acc += __shfl_sync(FULLM, suf, 0);
    }
    if (cnt < 0) cnt = acc;        // total < TOPK: cut=0, take everything
    *cutO = cut; *cntO = cnt;
}

// Horizontal 3-max of a row held as float4-per-lane (32 lanes cover 128 cols).
__device__ __forceinline__ float4 hmax4(float4 v, int lane){
    float left  = __shfl_up_sync(FULLM, v.w, 1);
    float right = __shfl_down_sync(FULLM, v.x, 1);
    left  = (lane == 0)  ? NEG_INF : left;
    right = (lane == 31) ? NEG_INF : right;
    float4 h;
    h.x = fmaxf(fmaxf(left, v.x), v.y);
    h.y = fmaxf(fmaxf(v.x, v.y), v.z);
    h.z = fmaxf(fmaxf(v.y, v.z), v.w);
    h.w = fmaxf(fmaxf(v.z, v.w), right);
    return h;
}

// Emit keeps into a per-thread local buffer: NO warp collectives, NO atomics
// in the hot loop. Order is irrelevant downstream (hist+rank are set-ops).
__device__ __forceinline__ void emit_row_local(float4 v, float4 hp, float4 hc, float4 hn,
                                               int r, int lane, int ch,
                                               int& lcnt, unsigned long long* lbuf){
    float wm0 = fmaxf(fmaxf(hp.x, hc.x), hn.x);
    float wm1 = fmaxf(fmaxf(hp.y, hc.y), hn.y);
    float wm2 = fmaxf(fmaxf(hp.z, hc.z), hn.z);
    float wm3 = fmaxf(fmaxf(hp.w, hc.w), hn.w);
    const unsigned ib = (unsigned)(ch*HWN + r*WN + lane*4);
    if (v.x == wm0 && lcnt < LCAP)
        lbuf[lcnt++] = ((unsigned long long)__float_as_uint(v.x) << 32) | (unsigned)(~ib);
    if (v.y == wm1 && lcnt < LCAP)
        lbuf[lcnt++] = ((unsigned long long)__float_as_uint(v.y) << 32) | (unsigned)(~(ib+1));
    if (v.z == wm2 && lcnt < LCAP)
        lbuf[lcnt++] = ((unsigned long long)__float_as_uint(v.z) << 32) | (unsigned)(~(ib+2));
    if (v.w == wm3 && lcnt < LCAP)
        lbuf[lcnt++] = ((unsigned long long)__float_as_uint(v.w) << 32) | (unsigned)(~(ib+3));
}

// K1: 3x3 NMS + per-plane top-100 cut; survivors staged in shared, then ONE
// block atomic reserves a slice of the per-batch contiguous array; each written
// survivor is also REDG-counted into the per-batch level-1 histogram.
__global__ __launch_bounds__(256) void nms_kernel(const float* __restrict__ hm){
    __shared__ unsigned long long sbuf[SBUF];
    __shared__ unsigned long long sstage[SCMP];
    __shared__ int shist[NB1];
    __shared__ int scnt, scnt2, sCut, sBase;
    unsigned long long lbuf[LCAP];                 // local (LMEM), writes rare
    int lcnt = 0;
    const int plane = blockIdx.x;
    const int b  = plane / CN;
    const int ch = plane % CN;
    const int wid  = threadIdx.x >> 5;
    const int lane = threadIdx.x & 31;
    const unsigned lmask = (1u << lane) - 1u;
    const int r0 = wid * 16;
    const float* base = hm + (size_t)plane * HWN + lane*4;

    if (threadIdx.x == 0){ scnt = 0; scnt2 = 0; sCut = 0; }
    for (int i = threadIdx.x; i < NB1; i += 256) shist[i] = 0;
    __syncthreads();

    // ---- NMS: register-rolling separable 3x3 max (no warp collectives) ----
    float4 v_cur, v_next, h_prev, h_cur, h_next;
    if (r0 > 0){
        h_prev = hmax4(*(const float4*)(base + (size_t)(r0-1)*WN), lane);
    } else {
        h_prev = make_float4(NEG_INF, NEG_INF, NEG_INF, NEG_INF);
    }
    v_cur = *(const float4*)(base + (size_t)r0*WN);
    h_cur = hmax4(v_cur, lane);

    #pragma unroll 3
    for (int r = r0; r < r0 + 15; ++r){
        v_next = *(const float4*)(base + (size_t)(r+1)*WN);
        h_next = hmax4(v_next, lane);
        emit_row_local(v_cur, h_prev, h_cur, h_next, r, lane, ch, lcnt, lbuf);
        h_prev = h_cur; h_cur = h_next; v_cur = v_next;
    }
    if (r0 + 16 < HN){
        h_next = hmax4(*(const float4*)(base + (size_t)(r0+16)*WN), lane);
    } else {
        h_next = make_float4(NEG_INF, NEG_INF, NEG_INF, NEG_INF);
    }
    emit_row_local(v_cur, h_prev, h_cur, h_next, r0+15, lane, ch, lcnt, lbuf);

    // ---- flush thread-local keeps to shared (one atomic per thread) ----
    int tbase = atomicAdd(&scnt, lcnt);
    for (int i = 0; i < lcnt; ++i){
        int p = tbase + i;
        if (p < SBUF) sbuf[p] = lbuf[i];
    }
    __syncthreads();

    // ---- per-plane histogram (uniform pass) -> plane cut ----
    const int nc = (scnt > SBUF) ? SBUF : scnt;
    for (int i = threadIdx.x; i < nc; i += 256){
        float v = __uint_as_float((unsigned)(sbuf[i] >> 32));
        atomicAdd(&shist[bin1f(v)], 1);
    }
    __syncthreads();
    if (wid == 0){
        int cut, dummy;
        cut_scan2(shist, 0, lane, &cut, &dummy);
        if (lane == 0) sCut = cut;
    }
    __syncthreads();
    const int p1 = sCut;

    // ---- compact plane survivors (bin >= p1) into shared staging ----
    for (int i0 = 0; i0 < nc; i0 += 256){
        const int i = i0 + threadIdx.x;
        const bool valid = (i < nc);
        unsigned long long kk = valid ? sbuf[i] : 0ull;
        int bin = bin1f(__uint_as_float((unsigned)(kk >> 32)));
        bool take = valid && (bin >= p1);
        unsigned bal = __ballot_sync(FULLM, take);
        int wb = 0;
        if (lane == 0 && bal) wb = atomicAdd(&scnt2, __popc(bal));
        wb = __shfl_sync(FULLM, wb, 0);
        if (take){
            int pos = wb + __popc(bal & lmask);
            if (pos < SCMP) sstage[pos] = kk;
        }
    }
    __syncthreads();
    const int total = (scnt2 > SCMP) ? SCMP : scnt2;
    if (threadIdx.x == 0) sBase = atomicAdd(&g_bcnt[b], total);
    __syncthreads();
    const int gbase = sBase;
    for (int i = threadIdx.x; i < total; i += 256){
        int gp = gbase + i;
        if (gp < BCAP2){
            unsigned long long kk = sstage[i];
            g_bcand[b][gp] = kk;
            float v = __uint_as_float((unsigned)(kk >> 32));
            atomicAdd(&g_hist[b][bin1f(v)], 1);       // REDG, no return
        }
    }
}

// K2: one block per batch; PDL-launched. Reads K1's level-1 histogram (and
// resets it), cuts b1 (+cntHi from the scan), then ONE 4-wide pass over the
// contiguous candidates doing compaction + level-2 sub-binning, cut b2,
// refined compact, rank ~101, decode.
__global__ __launch_bounds__(1024) void filter_rank_kernel(const float* __restrict__ offset,
                                                           const float* __restrict__ wh,
                                                           float* __restrict__ out){
    __shared__ int hist[NB1];       // level-1 (from global)
    __shared__ int hist2[NB1];      // level-2
    __shared__ unsigned long long sv[SCAP];
    __shared__ unsigned long long sv2[RCAP];
    __shared__ int sB1, sB2, sCol, sCol2, sCntHi;
    const int b    = blockIdx.x;
    const int tid  = threadIdx.x;
    const int wid  = tid >> 5;
    const int lane = tid & 31;
    const unsigned lmask = (1u << lane) - 1u;

    cudaGridDependencySynchronize();               // PDL: wait for nms completion

    if (tid == 0){ sCol = 0; sCol2 = 0; }
    for (int i = tid; i < NB1; i += 1024){
        int c = g_hist[b][i];
        hist[i] = c;
        hist2[i] = 0;
        if (c) g_hist[b][i] = 0;                   // consumer reset (write only if dirty)
    }
    int cnt = g_bcnt[b]; if (cnt > BCAP2) cnt = BCAP2;
    const unsigned long long* src = g_bcand[b];
    __syncthreads();
    if (wid == 0){
        int cut, cntge;
        cut_scan2(hist, 0, lane, &cut, &cntge);
        if (lane == 0){ sB1 = cut; sCntHi = cntge - hist[cut]; }
    }
    __syncthreads();
    const int b1 = sB1;

    // 4-wide pass: compact survivors (bin >= b1) AND build level-2 hist of bin==b1
    for (int i0 = 0; i0 < cnt; i0 += 4096){
        unsigned long long kk[4]; int bn[4]; bool tk[4];
        #pragma unroll
        for (int k = 0; k < 4; ++k){
            int i = i0 + k*1024 + tid;
            bool valid = (i < cnt);
            kk[k] = valid ? src[i] : 0ull;
            bn[k] = bin1f(__uint_as_float((unsigned)(kk[k] >> 32)));
            tk[k] = valid && (bn[k] >= b1);
        }
        unsigned bal[4]; int pc[4];
        #pragma unroll
        for (int k = 0; k < 4; ++k){ bal[k] = __ballot_sync(FULLM, tk[k]); pc[k] = __popc(bal[k]); }
        int tot = pc[0] + pc[1] + pc[2] + pc[3];
        int wb = 0;
        if (lane == 0 && tot) wb = atomicAdd(&sCol, tot);
        wb = __shfl_sync(FULLM, wb, 0);
        int off = 0;
        #pragma unroll
        for (int k = 0; k < 4; ++k){
            if (tk[k]){
                int pos = wb + off + __popc(bal[k] & lmask);
                if (pos < SCAP) sv[pos] = kk[k];
                if (bn[k] == b1)
                    atomicAdd(&hist2[bin2f(__uint_as_float((unsigned)(kk[k] >> 32)), b1)], 1);
            }
            off += pc[k];
        }
    }
    __syncthreads();
    const int m = (sCol > SCAP) ? SCAP : sCol;
    if (wid == 0){
        int cut, dummy;
        cut_scan2(hist2, sCntHi, lane, &cut, &dummy);
        if (lane == 0) sB2 = cut;
    }
    __syncthreads();
    const int b2 = sB2;

    // Compact refined set (~101 items). Ranks within it equal global ranks.
    for (int i0 = 0; i0 < m; i0 += 1024){
        const int i = i0 + tid;
        const bool valid = (i < m);
        unsigned long long kk = valid ? sv[i] : 0ull;
        float v = __uint_as_float((unsigned)(kk >> 32));
        bool take = valid && ((bin1f(v) > b1) || (bin2f(v, b1) >= b2));
        unsigned bal = __ballot_sync(FULLM, take);
        int wb = 0;
        if (lane == 0 && bal) wb = atomicAdd(&sCol2, __popc(bal));
        wb = __shfl_sync(FULLM, wb, 0);
        if (take){
            int pos = wb + __popc(bal & lmask);
            if (pos < RCAP) sv2[pos] = kk;
        }
    }
    __syncthreads();
    const int m2 = (sCol2 > RCAP) ? RCAP : sCol2;

    for (int e = tid; e < m2; e += 1024){
        unsigned long long key = sv2[e];
        int rank = 0;
        for (int j = 0; j < m2; ++j) rank += (sv2[j] > key);
        if (rank < TOPK){
            unsigned vb = (unsigned)(key >> 32);
            int idx = (int)(~(unsigned)key);
            float score = __uint_as_float(vb);
            int chn = idx / HWN;
            int spatial = idx - chn*HWN;
            int ys = spatial >> 7, xs = spatial & (WN-1);
            const float* offb = offset + (size_t)b * 2 * HWN;
            const float* whb  = wh     + (size_t)b * 2 * HWN;
            float ox = offb[spatial], oy = offb[HWN + spatial];
            float ww = whb[spatial],  hh = whb[HWN + spatial];
            float cx = (float)xs + ox, cy = (float)ys + oy;
            float hw2 = ww * 0.5f, hh2 = hh * 0.5f;

            float* out_ids = out;                 // (B,100,1)
            float* out_sc  = out + BN*TOPK;       // (B,100,1)
            float* out_bb  = out + 2*BN*TOPK;     // (B,100,4)
            out_ids[b*TOPK + rank] = (float)chn;
            out_sc [b*TOPK + rank] = score;
            float* bbp = out_bb + (size_t)(b*TOPK + rank)*4;
            bbp[0] = (cx - hw2)*4.0f;
            bbp[1] = (cy - hh2)*4.0f;
            bbp[2] = (cx + hw2)*4.0f;
            bbp[3] = (cy + hh2)*4.0f;
        }
    }

    // consumer reset so the next replay starts from a clean counter
    __syncthreads();
    if (tid == 0) g_bcnt[b] = 0;
}

extern "C" void kernel_launch(void* const* d_in, const int* in_sizes, int n_in,
                              void* d_out, int out_size){
    const float* hm     = (const float*)d_in[0];
    const float* offset = (const float*)d_in[1];
    const float* wh     = (const float*)d_in[2];
    float* out = (float*)d_out;

    nms_kernel<<<NPLANES, 256>>>(hm);

    // PDL launch: K2 setup overlaps K1's tail; data dependency enforced by
    // cudaGridDependencySynchronize() inside the kernel.
    cudaLaunchConfig_t cfg = {};
    cfg.gridDim  = dim3(BN, 1, 1);
    cfg.blockDim = dim3(1024, 1, 1);
    cfg.dynamicSmemBytes = 0;
    cfg.stream = 0;
    cudaLaunchAttribute attr[1];
    attr[0].id = cudaLaunchAttributeProgrammaticStreamSerialization;
    attr[0].val.programmaticStreamSerializationAllowed = 1;
    cfg.attrs = attr;
    cfg.numAttrs = 1;
    cudaLaunchKernelEx(&cfg, filter_rank_kernel, offset, wh, out);
}

// round 17
// speedup vs baseline: 1.0767x; 1.0767x over previous
#include <cuda_runtime.h>

#define BN   16
#define CN   80
#define HN   128
#define WN   128
#define HWN  (HN*WN)
#define NPLANES (BN*CN)
#define TOPK 100
#define NB1  2048
#define SBUF 2560                   // shared candidate cap per plane (expected ~1820)
#define BCAP2 16384                 // per-batch contiguous candidate cap (expected ~10.4k)
#define SCAP 2048                   // per-batch survivor cap (expected ~700)
#define RCAP 1024                   // refined cap (expected ~101)
#define FULLM 0xffffffffu
#define NEG_INF __int_as_float(0xff800000)

// ---- scratch (device globals; allocation-free contract) ----
__device__ unsigned long long g_bcand[BN][BCAP2]; // contiguous per-batch candidates
__device__ int g_bcnt[BN];                        // zero at load; consumer-reset by K2
__device__ int g_hist[BN][NB1];                   // zero at load; consumer-reset by K2

__device__ __forceinline__ int bin1f(float v){
    int b = (int)(v * 2048.0f);
    return b < 0 ? 0 : (b > NB1-1 ? NB1-1 : b);
}
__device__ __forceinline__ int bin2f(float v, int b1){
    float f = v * 2048.0f - (float)b1;
    int b = (int)(f * 2048.0f);
    return b < 0 ? 0 : (b > NB1-1 ? NB1-1 : b);
}

// Warp-serial suffix cut scan: largest bin with initAcc+suffix >= TOPK,
// also returning the count at/above that bin. Call from one full warp.
__device__ __forceinline__ void cut_scan2(const int* h, int initAcc, int lane,
                                          int* cutO, int* cntO){
    int acc = initAcc, cut = 0, cnt = -1;
    for (int bb = NB1 - 32; bb >= 0; bb -= 32){
        int suf = h[bb + lane];
        #pragma unroll
        for (int off = 1; off < 32; off <<= 1){
            int t = __shfl_down_sync(FULLM, suf, off);
            if (lane + off < 32) suf += t;
        }
        unsigned bal = __ballot_sync(FULLM, acc + suf >= TOPK);
        if (bal){
            int L = 31 - __clz(bal);
            cut = bb + L;
            cnt = acc + __shfl_sync(FULLM, suf, L);
            break;
        }
        acc += __shfl_sync(FULLM, suf, 0);
    }
    if (cnt < 0) cnt = acc;        // total < TOPK: cut=0, take everything
    *cutO = cut; *cntO = cnt;
}

// Horizontal 3-max of a row held as float4-per-lane (32 lanes cover 128 cols).
__device__ __forceinline__ float4 hmax4(float4 v, int lane){
    float left  = __shfl_up_sync(FULLM, v.w, 1);
    float right = __shfl_down_sync(FULLM, v.x, 1);
    left  = (lane == 0)  ? NEG_INF : left;
    right = (lane == 31) ? NEG_INF : right;
    float4 h;
    h.x = fmaxf(fmaxf(left, v.x), v.y);
    h.y = fmaxf(fmaxf(v.x, v.y), v.z);
    h.z = fmaxf(fmaxf(v.y, v.z), v.w);
    h.w = fmaxf(fmaxf(v.z, v.w), right);
    return h;
}

// Emit keeps: 4 ballots + ONE warp atomic + STS per row (no divergent atomics,
// no local-memory buffering — R14/R16 lessons).
__device__ __forceinline__ void emit_row(float4 v, float4 hp, float4 hc, float4 hn,
                                         int r, int lane, unsigned lmask, int ch,
                                         int* scnt, unsigned long long* sbuf){
    float wm0 = fmaxf(fmaxf(hp.x, hc.x), hn.x);
    float wm1 = fmaxf(fmaxf(hp.y, hc.y), hn.y);
    float wm2 = fmaxf(fmaxf(hp.z, hc.z), hn.z);
    float wm3 = fmaxf(fmaxf(hp.w, hc.w), hn.w);
    bool k0 = (v.x == wm0), k1 = (v.y == wm1), k2 = (v.z == wm2), k3 = (v.w == wm3);
    unsigned b0 = __ballot_sync(FULLM, k0);
    unsigned b1 = __ballot_sync(FULLM, k1);
    unsigned b2 = __ballot_sync(FULLM, k2);
    unsigned b3 = __ballot_sync(FULLM, k3);
    if (b0 | b1 | b2 | b3){                            // warp-uniform branch
        int c0 = __popc(b0), c1 = __popc(b1), c2 = __popc(b2);
        int total = c0 + c1 + c2 + __popc(b3);
        int base = 0;
        if (lane == 0) base = atomicAdd(scnt, total);
        base = __shfl_sync(FULLM, base, 0);
        const unsigned ib = (unsigned)(ch*HWN + r*WN + lane*4);
        if (k0){ int p = base + __popc(b0 & lmask);
                 if (p < SBUF) sbuf[p] = ((unsigned long long)__float_as_uint(v.x) << 32) | (unsigned)(~ib); }
        if (k1){ int p = base + c0 + __popc(b1 & lmask);
                 if (p < SBUF) sbuf[p] = ((unsigned long long)__float_as_uint(v.y) << 32) | (unsigned)(~(ib+1)); }
        if (k2){ int p = base + c0 + c1 + __popc(b2 & lmask);
                 if (p < SBUF) sbuf[p] = ((unsigned long long)__float_as_uint(v.z) << 32) | (unsigned)(~(ib+2)); }
        if (k3){ int p = base + c0 + c1 + c2 + __popc(b3 & lmask);
                 if (p < SBUF) sbuf[p] = ((unsigned long long)__float_as_uint(v.w) << 32) | (unsigned)(~(ib+3)); }
    }
}

// K1: 3x3 NMS + per-plane top-100 cut. Slice of the per-batch contiguous
// array reserved up-front from cut_scan2's count; survivors written DIRECTLY
// to global (no staging pass, -8KB smem).
__global__ __launch_bounds__(256) void nms_kernel(const float* __restrict__ hm){
    __shared__ unsigned long long sbuf[SBUF];
    __shared__ int shist[NB1];
    __shared__ int scnt, scnt2, sCut, sBase;
    const int plane = blockIdx.x;
    const int b  = plane / CN;
    const int ch = plane % CN;
    const int wid  = threadIdx.x >> 5;
    const int lane = threadIdx.x & 31;
    const unsigned lmask = (1u << lane) - 1u;
    const int r0 = wid * 16;
    const float* base = hm + (size_t)plane * HWN + lane*4;

    if (threadIdx.x == 0){ scnt = 0; scnt2 = 0; }
    for (int i = threadIdx.x; i < NB1; i += 256) shist[i] = 0;
    __syncthreads();

    // ---- NMS: register-rolling separable 3x3 max ----
    float4 v_cur, v_next, h_prev, h_cur, h_next;
    if (r0 > 0){
        h_prev = hmax4(*(const float4*)(base + (size_t)(r0-1)*WN), lane);
    } else {
        h_prev = make_float4(NEG_INF, NEG_INF, NEG_INF, NEG_INF);
    }
    v_cur = *(const float4*)(base + (size_t)r0*WN);
    h_cur = hmax4(v_cur, lane);

    #pragma unroll 3
    for (int r = r0; r < r0 + 15; ++r){
        v_next = *(const float4*)(base + (size_t)(r+1)*WN);
        h_next = hmax4(v_next, lane);
        emit_row(v_cur, h_prev, h_cur, h_next, r, lane, lmask, ch, &scnt, sbuf);
        h_prev = h_cur; h_cur = h_next; v_cur = v_next;
    }
    if (r0 + 16 < HN){
        h_next = hmax4(*(const float4*)(base + (size_t)(r0+16)*WN), lane);
    } else {
        h_next = make_float4(NEG_INF, NEG_INF, NEG_INF, NEG_INF);
    }
    emit_row(v_cur, h_prev, h_cur, h_next, r0+15, lane, lmask, ch, &scnt, sbuf);

    // ---- per-plane histogram (uniform pass) -> plane cut + count ----
    __syncthreads();
    const int nc = (scnt > SBUF) ? SBUF : scnt;
    for (int i = threadIdx.x; i < nc; i += 256){
        float v = __uint_as_float((unsigned)(sbuf[i] >> 32));
        atomicAdd(&shist[bin1f(v)], 1);
    }
    __syncthreads();
    if (wid == 0){
        int cut, cntge;
        cut_scan2(shist, 0, lane, &cut, &cntge);
        if (lane == 0){
            sCut = cut;
            sBase = atomicAdd(&g_bcnt[b], cntge);   // reserve slice up-front
        }
    }
    __syncthreads();
    const int p1 = sCut;
    const int gbase = sBase;

    // ---- compact plane survivors (bin >= p1) DIRECTLY to global ----
    for (int i0 = 0; i0 < nc; i0 += 256){
        const int i = i0 + threadIdx.x;
        const bool valid = (i < nc);
        unsigned long long kk = valid ? sbuf[i] : 0ull;
        int bin = bin1f(__uint_as_float((unsigned)(kk >> 32)));
        bool take = valid && (bin >= p1);
        unsigned bal = __ballot_sync(FULLM, take);
        int wb = 0;
        if (lane == 0 && bal) wb = atomicAdd(&scnt2, __popc(bal));
        wb = __shfl_sync(FULLM, wb, 0);
        if (take){
            int gp = gbase + wb + __popc(bal & lmask);
            if (gp < BCAP2){
                g_bcand[b][gp] = kk;
                atomicAdd(&g_hist[b][bin], 1);       // REDG, no return
            }
        }
    }
}

// K2: one block per batch; PDL-launched. Reads K1's level-1 histogram (and
// resets it), cuts b1 (+cntHi from the scan), then ONE 4-wide pass over the
// contiguous candidates doing compaction + level-2 sub-binning, cut b2,
// refined compact, rank ~101, decode.
__global__ __launch_bounds__(1024) void filter_rank_kernel(const float* __restrict__ offset,
                                                           const float* __restrict__ wh,
                                                           float* __restrict__ out){
    __shared__ int hist[NB1];       // level-1 (from global)
    __shared__ int hist2[NB1];      // level-2
    __shared__ unsigned long long sv[SCAP];
    __shared__ unsigned long long sv2[RCAP];
    __shared__ int sB1, sB2, sCol, sCol2, sCntHi;
    const int b    = blockIdx.x;
    const int tid  = threadIdx.x;
    const int wid  = tid >> 5;
    const int lane = tid & 31;
    const unsigned lmask = (1u << lane) - 1u;

    cudaGridDependencySynchronize();               // PDL: wait for nms completion

    if (tid == 0){ sCol = 0; sCol2 = 0; }
    for (int i = tid; i < NB1; i += 1024){
        int c = g_hist[b][i];
        hist[i] = c;
        hist2[i] = 0;
        if (c) g_hist[b][i] = 0;                   // consumer reset (write only if dirty)
    }
    int cnt = g_bcnt[b]; if (cnt > BCAP2) cnt = BCAP2;
    const unsigned long long* src = g_bcand[b];
    __syncthreads();
    if (wid == 0){
        int cut, cntge;
        cut_scan2(hist, 0, lane, &cut, &cntge);
        if (lane == 0){ sB1 = cut; sCntHi = cntge - hist[cut]; }
    }
    __syncthreads();
    const int b1 = sB1;

    // 4-wide pass: compact survivors (bin >= b1) AND build level-2 hist of bin==b1
    for (int i0 = 0; i0 < cnt; i0 += 4096){
        unsigned long long kk[4]; int bn[4]; bool tk[4];
        #pragma unroll
        for (int k = 0; k < 4; ++k){
            int i = i0 + k*1024 + tid;
            bool valid = (i < cnt);
            kk[k] = valid ? src[i] : 0ull;
            bn[k] = bin1f(__uint_as_float((unsigned)(kk[k] >> 32)));
            tk[k] = valid && (bn[k] >= b1);
        }
        unsigned bal[4]; int pc[4];
        #pragma unroll
        for (int k = 0; k < 4; ++k){ bal[k] = __ballot_sync(FULLM, tk[k]); pc[k] = __popc(bal[k]); }
        int tot = pc[0] + pc[1] + pc[2] + pc[3];
        int wb = 0;
        if (lane == 0 && tot) wb = atomicAdd(&sCol, tot);
        wb = __shfl_sync(FULLM, wb, 0);
        int off = 0;
        #pragma unroll
        for (int k = 0; k < 4; ++k){
            if (tk[k]){
                int pos = wb + off + __popc(bal[k] & lmask);
                if (pos < SCAP) sv[pos] = kk[k];
                if (bn[k] == b1)
                    atomicAdd(&hist2[bin2f(__uint_as_float((unsigned)(kk[k] >> 32)), b1)], 1);
            }
            off += pc[k];
        }
    }
    __syncthreads();
    const int m = (sCol > SCAP) ? SCAP : sCol;
    if (wid == 0){
        int cut, dummy;
        cut_scan2(hist2, sCntHi, lane, &cut, &dummy);
        if (lane == 0) sB2 = cut;
    }
    __syncthreads();
    const int b2 = sB2;

    // Compact refined set (~101 items). Ranks within it equal global ranks.
    for (int i0 = 0; i0 < m; i0 += 1024){
        const int i = i0 + tid;
        const bool valid = (i < m);
        unsigned long long kk = valid ? sv[i] : 0ull;
        float v = __uint_as_float((unsigned)(kk >> 32));
        bool take = valid && ((bin1f(v) > b1) || (bin2f(v, b1) >= b2));
        unsigned bal = __ballot_sync(FULLM, take);
        int wb = 0;
        if (lane == 0 && bal) wb = atomicAdd(&sCol2, __popc(bal));
        wb = __shfl_sync(FULLM, wb, 0);
        if (take){
            int pos = wb + __popc(bal & lmask);
            if (pos < RCAP) sv2[pos] = kk;
        }
    }
    __syncthreads();
    const int m2 = (sCol2 > RCAP) ? RCAP : sCol2;

    for (int e = tid; e < m2; e += 1024){
        unsigned long long key = sv2[e];
        int rank = 0;
        for (int j = 0; j < m2; ++j) rank += (sv2[j] > key);
        if (rank < TOPK){
            unsigned vb = (unsigned)(key >> 32);
            int idx = (int)(~(unsigned)key);
            float score = __uint_as_float(vb);
            int chn = idx / HWN;
            int spatial = idx - chn*HWN;
            int ys = spatial >> 7, xs = spatial & (WN-1);
            const float* offb = offset + (size_t)b * 2 * HWN;
            const float* whb  = wh     + (size_t)b * 2 * HWN;
            float ox = offb[spatial], oy = offb[HWN + spatial];
            float ww = whb[spatial],  hh = whb[HWN + spatial];
            float cx = (float)xs + ox, cy = (float)ys + oy;
            float hw2 = ww * 0.5f, hh2 = hh * 0.5f;

            float* out_ids = out;                 // (B,100,1)
            float* out_sc  = out + BN*TOPK;       // (B,100,1)
            float* out_bb  = out + 2*BN*TOPK;     // (B,100,4)
            out_ids[b*TOPK + rank] = (float)chn;
            out_sc [b*TOPK + rank] = score;
            float* bbp = out_bb + (size_t)(b*TOPK + rank)*4;
            bbp[0] = (cx - hw2)*4.0f;
            bbp[1] = (cy - hh2)*4.0f;
            bbp[2] = (cx + hw2)*4.0f;
            bbp[3] = (cy + hh2)*4.0f;
        }
    }

    // consumer reset so the next replay starts from a clean counter
    __syncthreads();
    if (tid == 0) g_bcnt[b] = 0;
}

extern "C" void kernel_launch(void* const* d_in, const int* in_sizes, int n_in,
                              void* d_out, int out_size){
    const float* hm     = (const float*)d_in[0];
    const float* offset = (const float*)d_in[1];
    const float* wh     = (const float*)d_in[2];
    float* out = (float*)d_out;

    nms_kernel<<<NPLANES, 256>>>(hm);

    // PDL launch: K2 setup overlaps K1's tail; data dependency enforced by
    // cudaGridDependencySynchronize() inside the kernel.
    cudaLaunchConfig_t cfg = {};
    cfg.gridDim  = dim3(BN, 1, 1);
    cfg.blockDim = dim3(1024, 1, 1);
    cfg.dynamicSmemBytes = 0;
    cfg.stream = 0;
    cudaLaunchAttribute attr[1];
    attr[0].id = cudaLaunchAttributeProgrammaticStreamSerialization;
    attr[0].val.programmaticStreamSerializationAllowed = 1;
    cfg.attrs = attr;
    cfg.numAttrs = 1;
    cudaLaunchKernelEx(&cfg, filter_rank_kernel, offset, wh, out);
}